// round 3
// baseline (speedup 1.0000x reference)
#include <cuda_runtime.h>

#define BB 64
#define II 512
#define HH 1024
#define NCHUNK 16              // h-dimension split for rec partials
#define HCHUNK (HH / NCHUNK)   // 64
#define BTILE 8                // batches per block in rec kernel
#define CROWS 8                // (b,h) rows per block in hebb update
#define CLIPV 2.0f
#define LN_EPS 1e-5f

// Scratch (no allocations allowed -> __device__ globals)
__device__ float g_rec_part[NCHUNK][BB][HH];   // 4 MB partial sums
__device__ float g_gemm[BB][HH];               // x @ fc_w^T
__device__ float g_etah[BB][HH];               // eta * h_post

// ---------------------------------------------------------------------------
// Kernel A: rec partials.
// rec[b,k] = sum_h h_pre[b,h] * (weight[h,k] + alpha[h,k]*hebb[b,h,k])
// Block = (h-chunk of 64, batch-group of 8). 256 threads, each owns one
// float4 of k. weight/alpha read once per 8 batches (L2 amortized); 8
// independent hebb streams per thread give MLP=8 on the DRAM-bound loads.
// ---------------------------------------------------------------------------
__global__ __launch_bounds__(256) void rec_partial_kernel(
    const float* __restrict__ h_pre, const float* __restrict__ hebb,
    const float* __restrict__ weight, const float* __restrict__ alpha)
{
    const int chunk = blockIdx.x;        // 0..NCHUNK-1
    const int bg    = blockIdx.y;        // 0..7
    const int tid   = threadIdx.x;       // 0..255 -> float4 lane over k
    const int b0    = bg * BTILE;
    const int h0    = chunk * HCHUNK;

    __shared__ float hp[BTILE][HCHUNK];
    {
        // 256 threads load BTILE*HCHUNK = 512 values in 2 steps
        for (int v = tid; v < BTILE * HCHUNK; v += 256) {
            int j  = v / HCHUNK;
            int hh = v % HCHUNK;
            hp[j][hh] = h_pre[(b0 + j) * HH + h0 + hh];
        }
    }
    __syncthreads();

    const float4* w4 = reinterpret_cast<const float4*>(weight);
    const float4* a4 = reinterpret_cast<const float4*>(alpha);
    const float4* e4 = reinterpret_cast<const float4*>(hebb);

    float4 acc[BTILE];
#pragma unroll
    for (int j = 0; j < BTILE; ++j) acc[j] = make_float4(0.f, 0.f, 0.f, 0.f);

    const float4* pj[BTILE];
#pragma unroll
    for (int j = 0; j < BTILE; ++j)
        pj[j] = e4 + ((b0 + j) * HH + h0) * (HH / 4) + tid;

    for (int hi = 0; hi < HCHUNK; ++hi) {
        const int h = h0 + hi;
        const float4 w = w4[h * (HH / 4) + tid];
        const float4 a = a4[h * (HH / 4) + tid];
#pragma unroll
        for (int j = 0; j < BTILE; ++j) {
            const float4 e = pj[j][hi * (HH / 4)];
            const float  s = hp[j][hi];
            acc[j].x += s * fmaf(a.x, e.x, w.x);
            acc[j].y += s * fmaf(a.y, e.y, w.y);
            acc[j].z += s * fmaf(a.z, e.z, w.z);
            acc[j].w += s * fmaf(a.w, e.w, w.w);
        }
    }

#pragma unroll
    for (int j = 0; j < BTILE; ++j) {
        float4* dst = reinterpret_cast<float4*>(&g_rec_part[chunk][b0 + j][0]);
        dst[tid] = acc[j];
    }
}

// ---------------------------------------------------------------------------
// Kernel B1: g_gemm[b,k] = sum_i x[b,i] * fc_w[k,i]   (64x1024x512, tiny)
// 16 blocks, each computes a 64x64 tile of C with 32-wide i-steps in smem.
// ---------------------------------------------------------------------------
__global__ __launch_bounds__(256) void gemm_kernel(
    const float* __restrict__ x, const float* __restrict__ fc_w)
{
    __shared__ float xs[64][33];
    __shared__ float ws[64][33];
    const int k0  = blockIdx.x * 64;
    const int tid = threadIdx.x;
    const int tx  = tid & 15;   // k sub-tile
    const int ty  = tid >> 4;   // b sub-tile

    float acc[4][4];
#pragma unroll
    for (int i = 0; i < 4; ++i)
#pragma unroll
        for (int j = 0; j < 4; ++j) acc[i][j] = 0.f;

    for (int i0 = 0; i0 < II; i0 += 32) {
        __syncthreads();
#pragma unroll
        for (int r = 0; r < 8; ++r) {
            int idx = tid + r * 256;
            int row = idx >> 5;   // 0..63
            int col = idx & 31;   // 0..31
            xs[row][col] = x[row * II + i0 + col];
            ws[row][col] = fc_w[(k0 + row) * II + i0 + col];
        }
        __syncthreads();
#pragma unroll
        for (int ii = 0; ii < 32; ++ii) {
            float xv[4], wv[4];
#pragma unroll
            for (int q = 0; q < 4; ++q) { xv[q] = xs[ty * 4 + q][ii]; wv[q] = ws[tx * 4 + q][ii]; }
#pragma unroll
            for (int bi = 0; bi < 4; ++bi)
#pragma unroll
                for (int ki = 0; ki < 4; ++ki)
                    acc[bi][ki] = fmaf(xv[bi], wv[ki], acc[bi][ki]);
        }
    }

#pragma unroll
    for (int bi = 0; bi < 4; ++bi)
#pragma unroll
        for (int ki = 0; ki < 4; ++ki)
            g_gemm[ty * 4 + bi][k0 + tx * 4 + ki] = acc[bi][ki];
}

// ---------------------------------------------------------------------------
// Kernel B2: per-batch fused epilogue.
// pre = gemm + fc_b + sum(rec partials); LN; tanh -> h_post (out);
// m = tanh(dot(h_post, mod_w) + mod_b) (out); etah = (m*modf_w+modf_b)*h_post
// One block per batch, 256 threads, each owns a float4 of k.
// ---------------------------------------------------------------------------
__device__ __forceinline__ float block_reduce_sum(float v, float* sred, int tid)
{
#pragma unroll
    for (int o = 16; o > 0; o >>= 1) v += __shfl_down_sync(0xffffffffu, v, o);
    if ((tid & 31) == 0) sred[tid >> 5] = v;
    __syncthreads();
    if (tid < 8) {
        float x = sred[tid];
#pragma unroll
        for (int o = 4; o > 0; o >>= 1) x += __shfl_down_sync(0xffu, x, o);
        if (tid == 0) sred[0] = x;
    }
    __syncthreads();
    float r = sred[0];
    __syncthreads();   // protect sred for next reduction
    return r;
}

__global__ __launch_bounds__(256) void ln_mod_kernel(
    const float* __restrict__ fc_b,
    const float* __restrict__ ln_g,  const float* __restrict__ ln_b,
    const float* __restrict__ mod_w, const float* __restrict__ mod_b,
    const float* __restrict__ modf_w, const float* __restrict__ modf_b,
    float* __restrict__ out_hpost, float* __restrict__ out_m)
{
    const int b   = blockIdx.x;
    const int tid = threadIdx.x;
    __shared__ float sred[8];
    __shared__ float sm;

    // pre = gemm + fc_b + sum of NCHUNK rec partials
    float4 v  = reinterpret_cast<const float4*>(&g_gemm[b][0])[tid];
    float4 fb = reinterpret_cast<const float4*>(fc_b)[tid];
    v.x += fb.x; v.y += fb.y; v.z += fb.z; v.w += fb.w;
#pragma unroll
    for (int c = 0; c < NCHUNK; ++c) {
        float4 p = reinterpret_cast<const float4*>(&g_rec_part[c][b][0])[tid];
        v.x += p.x; v.y += p.y; v.z += p.z; v.w += p.w;
    }

    float s  = v.x + v.y + v.z + v.w;
    float s2 = v.x * v.x + v.y * v.y + v.z * v.z + v.w * v.w;
    s  = block_reduce_sum(s,  sred, tid);
    s2 = block_reduce_sum(s2, sred, tid);
    const float mu   = s / (float)HH;
    const float var  = s2 / (float)HH - mu * mu;
    const float rstd = rsqrtf(var + LN_EPS);

    float4 g  = reinterpret_cast<const float4*>(ln_g)[tid];
    float4 be = reinterpret_cast<const float4*>(ln_b)[tid];
    float4 hp;
    hp.x = tanhf((v.x - mu) * rstd * g.x + be.x);
    hp.y = tanhf((v.y - mu) * rstd * g.y + be.y);
    hp.z = tanhf((v.z - mu) * rstd * g.z + be.z);
    hp.w = tanhf((v.w - mu) * rstd * g.w + be.w);
    reinterpret_cast<float4*>(out_hpost + b * HH)[tid] = hp;

    // m = tanh(dot(h_post, mod_w) + mod_b)
    float4 mw = reinterpret_cast<const float4*>(mod_w)[tid];
    float d = hp.x * mw.x + hp.y * mw.y + hp.z * mw.z + hp.w * mw.w;
    d = block_reduce_sum(d, sred, tid);
    if (tid == 0) {
        float m = tanhf(d + mod_b[0]);
        out_m[b] = m;
        sm = m;
    }
    __syncthreads();
    const float m = sm;

    // etah[b,k] = (m*modf_w[k] + modf_b[k]) * h_post[b,k]
    float4 fw  = reinterpret_cast<const float4*>(modf_w)[tid];
    float4 fbb = reinterpret_cast<const float4*>(modf_b)[tid];
    float4 t;
    t.x = fmaf(m, fw.x, fbb.x) * hp.x;
    t.y = fmaf(m, fw.y, fbb.y) * hp.y;
    t.z = fmaf(m, fw.z, fbb.z) * hp.z;
    t.w = fmaf(m, fw.w, fbb.w) * hp.w;
    reinterpret_cast<float4*>(&g_etah[b][0])[tid] = t;
}

// ---------------------------------------------------------------------------
// Kernel C: hebb_new[b,h,k] = clip(hebb[b,h,k] + h_pre[b,h]*etah[b,k])
// Pure stream: CROWS (b,h) rows per block, float4 per thread, MLP=CROWS.
// ---------------------------------------------------------------------------
__global__ __launch_bounds__(256) void hebb_update_kernel(
    const float* __restrict__ h_pre, const float* __restrict__ hebb,
    float* __restrict__ out_hebb)
{
    const int row0 = blockIdx.x * CROWS;
    const int tid  = threadIdx.x;
#pragma unroll
    for (int r = 0; r < CROWS; ++r) {
        const int bh = row0 + r;
        const int b  = bh >> 10;
        const float hpv = __ldg(&h_pre[bh]);   // h_pre[b*H + h] == h_pre[bh]
        const float4 e = reinterpret_cast<const float4*>(hebb)[bh * (HH / 4) + tid];
        const float4 t = reinterpret_cast<const float4*>(&g_etah[b][0])[tid];
        float4 o;
        o.x = fminf(fmaxf(fmaf(hpv, t.x, e.x), -CLIPV), CLIPV);
        o.y = fminf(fmaxf(fmaf(hpv, t.y, e.y), -CLIPV), CLIPV);
        o.z = fminf(fmaxf(fmaf(hpv, t.z, e.z), -CLIPV), CLIPV);
        o.w = fminf(fmaxf(fmaf(hpv, t.w, e.w), -CLIPV), CLIPV);
        reinterpret_cast<float4*>(out_hebb)[bh * (HH / 4) + tid] = o;
    }
}

// ---------------------------------------------------------------------------
// Launch. Inputs in metadata order:
// 0 x, 1 h_pre, 2 hebb, 3 fc_w, 4 fc_b, 5 weight, 6 alpha,
// 7 ln_g, 8 ln_b, 9 mod_w, 10 mod_b, 11 modf_w, 12 modf_b
// Output: h_post [64*1024] | m [64] | hebb_new [64*1024*1024], fp32.
// ---------------------------------------------------------------------------
extern "C" void kernel_launch(void* const* d_in, const int* in_sizes, int n_in,
                              void* d_out, int out_size)
{
    const float* x      = (const float*)d_in[0];
    const float* h_pre  = (const float*)d_in[1];
    const float* hebb   = (const float*)d_in[2];
    const float* fc_w   = (const float*)d_in[3];
    const float* fc_b   = (const float*)d_in[4];
    const float* weight = (const float*)d_in[5];
    const float* alpha  = (const float*)d_in[6];
    const float* ln_g   = (const float*)d_in[7];
    const float* ln_b   = (const float*)d_in[8];
    const float* mod_w  = (const float*)d_in[9];
    const float* mod_b  = (const float*)d_in[10];
    const float* modf_w = (const float*)d_in[11];
    const float* modf_b = (const float*)d_in[12];

    float* out       = (float*)d_out;
    float* out_hpost = out;                 // 64*1024
    float* out_m     = out + BB * HH;       // 64
    float* out_hebb  = out + BB * HH + BB;  // 64*1024*1024

    rec_partial_kernel<<<dim3(NCHUNK, BB / BTILE), 256>>>(h_pre, hebb, weight, alpha);
    gemm_kernel<<<HH / 64, 256>>>(x, fc_w);
    ln_mod_kernel<<<BB, 256>>>(fc_b, ln_g, ln_b, mod_w, mod_b, modf_w, modf_b,
                               out_hpost, out_m);
    hebb_update_kernel<<<(BB * HH) / CROWS, 256>>>(h_pre, hebb, out_hebb);
}

// round 5
// speedup vs baseline: 1.9064x; 1.9064x over previous
#include <cuda_runtime.h>

#define BB 64
#define II 512
#define HH 1024
#define NCHUNK 32              // h-dimension split for rec partials
#define HCHUNK (HH / NCHUNK)   // 32
#define BTILE 4                // batches per block in rec kernel
#define BGROUPS (BB / BTILE)   // 16
#define CROWS 8                // (b,h) rows per block in hebb update
#define CLIPV 2.0f
#define LN_EPS 1e-5f

// Scratch (no allocations allowed -> __device__ globals)
__device__ float g_rec_part[NCHUNK][BB][HH];   // 8 MB partial sums
__device__ float g_gemm[BB][HH];               // x @ fc_w^T
__device__ float g_etah[BB][HH];               // eta * h_post

__device__ __forceinline__ float4 ldcs4(const float4* p)
{
    float4 v;
    asm volatile("ld.global.cs.v4.f32 {%0,%1,%2,%3}, [%4];"
                 : "=f"(v.x), "=f"(v.y), "=f"(v.z), "=f"(v.w) : "l"(p));
    return v;
}

__device__ __forceinline__ void stcs4(float4* p, float4 v)
{
    asm volatile("st.global.cs.v4.f32 [%0], {%1,%2,%3,%4};"
                 :: "l"(p), "f"(v.x), "f"(v.y), "f"(v.z), "f"(v.w));
}

// ---------------------------------------------------------------------------
// Kernel A: rec partials.
// rec[b,k] = sum_h h_pre[b,h] * (weight[h,k] + alpha[h,k]*hebb[b,h,k])
// Block = (h-chunk of 32, batch-group of 4). Grid = 32 x 16 = 512 blocks,
// 256 threads (one float4 k-lane each). ~3.5 blocks/SM -> ~28 warps/SM, and
// unroll-2 over h gives ~12 independent loads per issue batch: enough MLP
// to saturate DRAM (R3-measured version had 128 blocks / 8 warps/SM -> 1 TB/s).
// weight/alpha amortized over 4 batches (128 MB L2 leg, under DRAM leg).
// ---------------------------------------------------------------------------
__global__ __launch_bounds__(256) void rec_partial_kernel(
    const float* __restrict__ h_pre, const float* __restrict__ hebb,
    const float* __restrict__ weight, const float* __restrict__ alpha)
{
    const int chunk = blockIdx.x;        // 0..NCHUNK-1
    const int bg    = blockIdx.y;        // 0..BGROUPS-1
    const int tid   = threadIdx.x;       // 0..255 -> float4 lane over k
    const int b0    = bg * BTILE;
    const int h0    = chunk * HCHUNK;

    __shared__ float hp[BTILE][HCHUNK];
    if (tid < BTILE * HCHUNK) {
        int j  = tid >> 5;               // 0..3
        int hh = tid & 31;               // 0..31
        hp[j][hh] = h_pre[(b0 + j) * HH + h0 + hh];
    }
    __syncthreads();

    const float4* w4 = reinterpret_cast<const float4*>(weight);
    const float4* a4 = reinterpret_cast<const float4*>(alpha);
    const float4* e4 = reinterpret_cast<const float4*>(hebb);

    float4 acc[BTILE];
#pragma unroll
    for (int j = 0; j < BTILE; ++j) acc[j] = make_float4(0.f, 0.f, 0.f, 0.f);

    const float4* pj[BTILE];
#pragma unroll
    for (int j = 0; j < BTILE; ++j)
        pj[j] = e4 + ((b0 + j) * HH + h0) * (HH / 4) + tid;

#pragma unroll 2
    for (int hi = 0; hi < HCHUNK; ++hi) {
        const int h = h0 + hi;
        const float4 w = w4[h * (HH / 4) + tid];
        const float4 a = a4[h * (HH / 4) + tid];
        float4 e[BTILE];
#pragma unroll
        for (int j = 0; j < BTILE; ++j)
            e[j] = ldcs4(pj[j] + hi * (HH / 4));
#pragma unroll
        for (int j = 0; j < BTILE; ++j) {
            const float s = hp[j][hi];
            acc[j].x += s * fmaf(a.x, e[j].x, w.x);
            acc[j].y += s * fmaf(a.y, e[j].y, w.y);
            acc[j].z += s * fmaf(a.z, e[j].z, w.z);
            acc[j].w += s * fmaf(a.w, e[j].w, w.w);
        }
    }

#pragma unroll
    for (int j = 0; j < BTILE; ++j) {
        float4* dst = reinterpret_cast<float4*>(&g_rec_part[chunk][b0 + j][0]);
        dst[tid] = acc[j];
    }
}

// ---------------------------------------------------------------------------
// Kernel B1: g_gemm[b,k] = sum_i x[b,i] * fc_w[k,i]   (64x1024x512, tiny)
// ---------------------------------------------------------------------------
__global__ __launch_bounds__(256) void gemm_kernel(
    const float* __restrict__ x, const float* __restrict__ fc_w)
{
    __shared__ float xs[64][33];
    __shared__ float ws[64][33];
    const int k0  = blockIdx.x * 64;
    const int tid = threadIdx.x;
    const int tx  = tid & 15;   // k sub-tile
    const int ty  = tid >> 4;   // b sub-tile

    float acc[4][4];
#pragma unroll
    for (int i = 0; i < 4; ++i)
#pragma unroll
        for (int j = 0; j < 4; ++j) acc[i][j] = 0.f;

    for (int i0 = 0; i0 < II; i0 += 32) {
        __syncthreads();
#pragma unroll
        for (int r = 0; r < 8; ++r) {
            int idx = tid + r * 256;
            int row = idx >> 5;   // 0..63
            int col = idx & 31;   // 0..31
            xs[row][col] = x[row * II + i0 + col];
            ws[row][col] = fc_w[(k0 + row) * II + i0 + col];
        }
        __syncthreads();
#pragma unroll
        for (int ii = 0; ii < 32; ++ii) {
            float xv[4], wv[4];
#pragma unroll
            for (int q = 0; q < 4; ++q) { xv[q] = xs[ty * 4 + q][ii]; wv[q] = ws[tx * 4 + q][ii]; }
#pragma unroll
            for (int bi = 0; bi < 4; ++bi)
#pragma unroll
                for (int ki = 0; ki < 4; ++ki)
                    acc[bi][ki] = fmaf(xv[bi], wv[ki], acc[bi][ki]);
        }
    }

#pragma unroll
    for (int bi = 0; bi < 4; ++bi)
#pragma unroll
        for (int ki = 0; ki < 4; ++ki)
            g_gemm[ty * 4 + bi][k0 + tx * 4 + ki] = acc[bi][ki];
}

// ---------------------------------------------------------------------------
// Kernel B2: per-batch fused epilogue.
// ---------------------------------------------------------------------------
__device__ __forceinline__ float block_reduce_sum(float v, float* sred, int tid)
{
#pragma unroll
    for (int o = 16; o > 0; o >>= 1) v += __shfl_down_sync(0xffffffffu, v, o);
    if ((tid & 31) == 0) sred[tid >> 5] = v;
    __syncthreads();
    if (tid < 8) {
        float x = sred[tid];
#pragma unroll
        for (int o = 4; o > 0; o >>= 1) x += __shfl_down_sync(0xffu, x, o);
        if (tid == 0) sred[0] = x;
    }
    __syncthreads();
    float r = sred[0];
    __syncthreads();   // protect sred for next reduction
    return r;
}

__global__ __launch_bounds__(256) void ln_mod_kernel(
    const float* __restrict__ fc_b,
    const float* __restrict__ ln_g,  const float* __restrict__ ln_b,
    const float* __restrict__ mod_w, const float* __restrict__ mod_b,
    const float* __restrict__ modf_w, const float* __restrict__ modf_b,
    float* __restrict__ out_hpost, float* __restrict__ out_m)
{
    const int b   = blockIdx.x;
    const int tid = threadIdx.x;
    __shared__ float sred[8];
    __shared__ float sm;

    // pre = gemm + fc_b + sum of NCHUNK rec partials
    float4 v  = reinterpret_cast<const float4*>(&g_gemm[b][0])[tid];
    float4 fb = reinterpret_cast<const float4*>(fc_b)[tid];
    v.x += fb.x; v.y += fb.y; v.z += fb.z; v.w += fb.w;
#pragma unroll
    for (int c = 0; c < NCHUNK; ++c) {
        float4 p = reinterpret_cast<const float4*>(&g_rec_part[c][b][0])[tid];
        v.x += p.x; v.y += p.y; v.z += p.z; v.w += p.w;
    }

    float s  = v.x + v.y + v.z + v.w;
    float s2 = v.x * v.x + v.y * v.y + v.z * v.z + v.w * v.w;
    s  = block_reduce_sum(s,  sred, tid);
    s2 = block_reduce_sum(s2, sred, tid);
    const float mu   = s / (float)HH;
    const float var  = s2 / (float)HH - mu * mu;
    const float rstd = rsqrtf(var + LN_EPS);

    float4 g  = reinterpret_cast<const float4*>(ln_g)[tid];
    float4 be = reinterpret_cast<const float4*>(ln_b)[tid];
    float4 hp;
    hp.x = tanhf((v.x - mu) * rstd * g.x + be.x);
    hp.y = tanhf((v.y - mu) * rstd * g.y + be.y);
    hp.z = tanhf((v.z - mu) * rstd * g.z + be.z);
    hp.w = tanhf((v.w - mu) * rstd * g.w + be.w);
    reinterpret_cast<float4*>(out_hpost + b * HH)[tid] = hp;

    // m = tanh(dot(h_post, mod_w) + mod_b)
    float4 mw = reinterpret_cast<const float4*>(mod_w)[tid];
    float d = hp.x * mw.x + hp.y * mw.y + hp.z * mw.z + hp.w * mw.w;
    d = block_reduce_sum(d, sred, tid);
    if (tid == 0) {
        float m = tanhf(d + mod_b[0]);
        out_m[b] = m;
        sm = m;
    }
    __syncthreads();
    const float m = sm;

    // etah[b,k] = (m*modf_w[k] + modf_b[k]) * h_post[b,k]
    float4 fw  = reinterpret_cast<const float4*>(modf_w)[tid];
    float4 fbb = reinterpret_cast<const float4*>(modf_b)[tid];
    float4 t;
    t.x = fmaf(m, fw.x, fbb.x) * hp.x;
    t.y = fmaf(m, fw.y, fbb.y) * hp.y;
    t.z = fmaf(m, fw.z, fbb.z) * hp.z;
    t.w = fmaf(m, fw.w, fbb.w) * hp.w;
    reinterpret_cast<float4*>(&g_etah[b][0])[tid] = t;
}

// ---------------------------------------------------------------------------
// Kernel C: hebb_new[b,h,k] = clip(hebb[b,h,k] + h_pre[b,h]*etah[b,k])
// Pure stream: CROWS rows per block, float4 per thread, streaming ld/st.
// R3-measured at 77% of HBM peak; unchanged apart from streaming hints.
// ---------------------------------------------------------------------------
__global__ __launch_bounds__(256) void hebb_update_kernel(
    const float* __restrict__ h_pre, const float* __restrict__ hebb,
    float* __restrict__ out_hebb)
{
    const int row0 = blockIdx.x * CROWS;
    const int tid  = threadIdx.x;
#pragma unroll
    for (int r = 0; r < CROWS; ++r) {
        const int bh = row0 + r;
        const int b  = bh >> 10;
        const float hpv = __ldg(&h_pre[bh]);   // h_pre[b*H + h] == h_pre[bh]
        const float4 e = ldcs4(reinterpret_cast<const float4*>(hebb) + bh * (HH / 4) + tid);
        const float4 t = reinterpret_cast<const float4*>(&g_etah[b][0])[tid];
        float4 o;
        o.x = fminf(fmaxf(fmaf(hpv, t.x, e.x), -CLIPV), CLIPV);
        o.y = fminf(fmaxf(fmaf(hpv, t.y, e.y), -CLIPV), CLIPV);
        o.z = fminf(fmaxf(fmaf(hpv, t.z, e.z), -CLIPV), CLIPV);
        o.w = fminf(fmaxf(fmaf(hpv, t.w, e.w), -CLIPV), CLIPV);
        stcs4(reinterpret_cast<float4*>(out_hebb) + bh * (HH / 4) + tid, o);
    }
}

// ---------------------------------------------------------------------------
// Launch. Inputs in metadata order:
// 0 x, 1 h_pre, 2 hebb, 3 fc_w, 4 fc_b, 5 weight, 6 alpha,
// 7 ln_g, 8 ln_b, 9 mod_w, 10 mod_b, 11 modf_w, 12 modf_b
// Output: h_post [64*1024] | m [64] | hebb_new [64*1024*1024], fp32.
// ---------------------------------------------------------------------------
extern "C" void kernel_launch(void* const* d_in, const int* in_sizes, int n_in,
                              void* d_out, int out_size)
{
    const float* x      = (const float*)d_in[0];
    const float* h_pre  = (const float*)d_in[1];
    const float* hebb   = (const float*)d_in[2];
    const float* fc_w   = (const float*)d_in[3];
    const float* fc_b   = (const float*)d_in[4];
    const float* weight = (const float*)d_in[5];
    const float* alpha  = (const float*)d_in[6];
    const float* ln_g   = (const float*)d_in[7];
    const float* ln_b   = (const float*)d_in[8];
    const float* mod_w  = (const float*)d_in[9];
    const float* mod_b  = (const float*)d_in[10];
    const float* modf_w = (const float*)d_in[11];
    const float* modf_b = (const float*)d_in[12];

    float* out       = (float*)d_out;
    float* out_hpost = out;                 // 64*1024
    float* out_m     = out + BB * HH;       // 64
    float* out_hebb  = out + BB * HH + BB;  // 64*1024*1024

    rec_partial_kernel<<<dim3(NCHUNK, BGROUPS), 256>>>(h_pre, hebb, weight, alpha);
    gemm_kernel<<<HH / 64, 256>>>(x, fc_w);
    ln_mod_kernel<<<BB, 256>>>(fc_b, ln_g, ln_b, mod_w, mod_b, modf_w, modf_b,
                               out_hpost, out_m);
    hebb_update_kernel<<<(BB * HH) / CROWS, 256>>>(h_pre, hebb, out_hebb);
}